// round 9
// baseline (speedup 1.0000x reference)
#include <cuda_runtime.h>
#include <cstdint>
#include <cstddef>

// Problem constants (fixed by the dataset)
#define E_DIM 128
#define S_DIM 64
#define P_DIM 256
#define B_DIM 4096
#define ROW_FLOATS (S_DIM * E_DIM)          // 8192 floats = 32 KB
#define ROW_BYTES  (ROW_FLOATS * 4)
#define N_STAGES   3
#define N_WARPS    16

// ---------------------------------------------------------------------------
// Shared-memory layout (dynamic):
//   [0,24)       mbarrier[3]
//   [32,292)     seg_start[65]
//   [304,2352)   meta int2[256]        (sorted by i3)
//   [2352,3376)  prep scratch s_i3[256]
//   [3376,3640)  prep scratch s_cnt[65]
//   [3648,3712)  warp seg-list counts  int[16]
//   [3712,5760)  warp seg-lists        ushort[16][64]
//   [8192 + st*65536) : stage st = [sx 32KB][sy 32KB]
// ---------------------------------------------------------------------------
#define OFF_MBAR   0
#define OFF_SEG    32
#define OFF_META   304
#define OFF_I3     2352
#define OFF_CNT    3376
#define OFF_WCNT   3648
#define OFF_WLIST  3712
#define OFF_STAGE  8192
#define STAGE_BYTES (2 * ROW_BYTES)
#define SMEM_BYTES (OFF_STAGE + N_STAGES * STAGE_BYTES)   // 204800

__device__ __forceinline__ uint32_t smem_u32(const void* p) {
    uint32_t a;
    asm("{ .reg .u64 t; cvta.to.shared.u64 t, %1; cvt.u32.u64 %0, t; }"
        : "=r"(a) : "l"(p));
    return a;
}

__device__ __forceinline__ void mbar_wait(uint32_t mbar, uint32_t parity) {
    uint32_t done;
    asm volatile(
        "{\n\t"
        ".reg .pred p;\n\t"
        "mbarrier.try_wait.parity.acquire.cta.shared::cta.b64 p, [%1], %2;\n\t"
        "selp.b32 %0, 1, 0, p;\n\t"
        "}" : "=r"(done) : "r"(mbar), "r"(parity) : "memory");
    if (!done) {
        asm volatile(
            "{\n\t"
            ".reg .pred P1;\n\t"
            "W_%=:\n\t"
            "mbarrier.try_wait.parity.acquire.cta.shared::cta.b64 P1, [%0], %1, 0x989680;\n\t"
            "@P1 bra.uni D_%=;\n\t"
            "bra.uni W_%=;\n\t"
            "D_%=:\n\t"
            "}" :: "r"(mbar), "r"(parity) : "memory");
    }
}

__device__ __forceinline__ void issue_row_copy(
    const char* smem, uint32_t mbar0, int stage,
    const float* x_table, const float* y, const int* x_idx, int r)
{
    const uint32_t mb = mbar0 + 8u * stage;
    asm volatile("mbarrier.arrive.expect_tx.shared.b64 _, [%0], %1;"
                 :: "r"(mb), "r"(STAGE_BYTES) : "memory");
    const uint32_t dst = smem_u32(smem + OFF_STAGE) + stage * STAGE_BYTES;
    const char* xsrc = (const char*)(x_table + (size_t)x_idx[r] * ROW_FLOATS);
    const char* ysrc = (const char*)(y + (size_t)r * ROW_FLOATS);
    asm volatile(
        "cp.async.bulk.shared::cta.global.mbarrier::complete_tx::bytes "
        "[%0], [%1], %2, [%3];"
        :: "r"(dst), "l"(xsrc), "r"(ROW_BYTES), "r"(mb) : "memory");
    asm volatile(
        "cp.async.bulk.shared::cta.global.mbarrier::complete_tx::bytes "
        "[%0], [%1], %2, [%3];"
        :: "r"(dst + ROW_BYTES), "l"(ysrc), "r"(ROW_BYTES), "r"(mb) : "memory");
}

__global__ __launch_bounds__(32 * N_WARPS, 1)
void seg_poly_main(const float* __restrict__ x_table,
                   const float* __restrict__ y,
                   const int*   __restrict__ x_idx,
                   const float* __restrict__ path_coeff,
                   const int*   __restrict__ path_idx,
                   float*       __restrict__ out)
{
    extern __shared__ char smem[];
    int*      sseg   = (int*)     (smem + OFF_SEG);
    int2*     smeta  = (int2*)    (smem + OFF_META);
    int*      s_i3   = (int*)     (smem + OFF_I3);
    int*      s_cnt  = (int*)     (smem + OFF_CNT);
    int*      s_wcnt = (int*)     (smem + OFF_WCNT);
    uint16_t* s_wlst = (uint16_t*)(smem + OFF_WLIST);

    const int t    = threadIdx.x;            // 0..511
    const int warp = t >> 5;                 // 0..15
    const int lane = t & 31;
    const int G    = gridDim.x;

    const uint32_t mbar0 = smem_u32(smem + OFF_MBAR);

    if (t < N_STAGES) {
        asm volatile("mbarrier.init.shared.b64 [%0], 1;"
                     :: "r"(mbar0 + 8u * t) : "memory");
    }
    if (t <= S_DIM) s_cnt[t] = 0;
    __syncthreads();

    // --- prologue: bulk copies for this CTA's first two rows ---------------
    const int r0 = blockIdx.x;
    if (t == 0) {
        #pragma unroll
        for (int u = 0; u < 2; u++) {
            const int r = r0 + u * G;
            if (r < B_DIM)
                issue_row_copy(smem, mbar0, u, x_table, y, x_idx, r);
        }
    }

    // --- inline prep: stable counting-sort of 256 paths by i3 --------------
    if (t < P_DIM) {
        const int i1 = path_idx[t * 3 + 0];
        const int i2 = path_idx[t * 3 + 1];
        const int i3 = path_idx[t * 3 + 2];
        s_i3[t] = i3;
        __syncthreads();
        atomicAdd(&s_cnt[i3 + 1], 1);
        __syncthreads();
        if (t == 0) {
            int acc = 0;
            #pragma unroll
            for (int i = 0; i <= S_DIM; i++) { acc += s_cnt[i]; s_cnt[i] = acc; }
        }
        __syncthreads();
        if (t <= S_DIM) sseg[t] = s_cnt[t];
        int rank = 0;                        // stable rank within segment
        for (int j = 0; j < t; j++) rank += (s_i3[j] == i3) ? 1 : 0;
        smeta[s_cnt[i3] + rank] =
            make_int2(((i1 * (E_DIM / 4)) << 16) | (i2 * (E_DIM / 4)),
                      __float_as_int(path_coeff[t]));
    } else {
        __syncthreads(); __syncthreads(); __syncthreads();
    }
    __syncthreads();

    // --- balanced warp<-segment schedule (thread 0, deterministic greedy) --
    if (t == 0) {
        int cnt[S_DIM];
        bool used[S_DIM];
        int load[N_WARPS], wc[N_WARPS];
        #pragma unroll
        for (int s = 0; s < S_DIM; s++) { cnt[s] = sseg[s+1] - sseg[s]; used[s] = false; }
        #pragma unroll
        for (int w = 0; w < N_WARPS; w++) { load[w] = 0; wc[w] = 0; }
        for (int it = 0; it < S_DIM; it++) {
            int bs = -1, bc = -1;
            for (int s = 0; s < S_DIM; s++)
                if (!used[s] && cnt[s] > bc) { bc = cnt[s]; bs = s; }
            int bw = 0, bl = load[0];
            #pragma unroll
            for (int w = 1; w < N_WARPS; w++)
                if (load[w] < bl) { bl = load[w]; bw = w; }
            used[bs] = true;
            s_wlst[bw * S_DIM + wc[bw]] = (uint16_t)bs;
            wc[bw]++;
            load[bw] += bc + 1;              // +1: per-segment fixed cost
        }
        #pragma unroll
        for (int w = 0; w < N_WARPS; w++) s_wcnt[w] = wc[w];
    }
    __syncthreads();

    const int       my_nseg = s_wcnt[warp];
    const uint16_t* my_list = s_wlst + warp * S_DIM;

    // --- main pipelined loop over this CTA's rows --------------------------
    int k = 0;
    for (int r = r0; r < B_DIM; r += G, k++) {
        const int st = k % N_STAGES;
        const int u  = k / N_STAGES;         // use-count of this stage

        // issue copy for row r + 2G into stage (k+2)%3 (freed 1 iter ago)
        const int rpre = r + 2 * G;
        if (t == 0 && rpre < B_DIM)
            issue_row_copy(smem, mbar0, (k + 2) % N_STAGES, x_table, y, x_idx, rpre);

        // wait for this row's data
        mbar_wait(mbar0 + 8u * st, u & 1);

        const float4* sx4 = (const float4*)(smem + OFF_STAGE + st * STAGE_BYTES);
        const float4* sy4 = sx4 + (ROW_FLOATS / 4);
        float4* o4 = (float4*)(out + (size_t)r * ROW_FLOATS);

        for (int ii = 0; ii < my_nseg; ii++) {
            const int s3  = my_list[ii];
            const int beg = sseg[s3];
            const int end = sseg[s3 + 1];
            float4 acc = make_float4(0.f, 0.f, 0.f, 0.f);
            #pragma unroll 4
            for (int j = beg; j < end; j++) {
                const int2  m  = smeta[j];          // LDS.64 broadcast
                const float c  = __int_as_float(m.y);
                const int   i1 = m.x >> 16;         // float4-unit offsets
                const int   i2 = m.x & 0xFFFF;
                const float4 xv = sx4[i1 + lane];   // LDS.128, conflict-free
                const float4 yv = sy4[i2 + lane];
                acc.x = fmaf(c * xv.x, yv.x, acc.x);
                acc.y = fmaf(c * xv.y, yv.y, acc.y);
                acc.z = fmaf(c * xv.z, yv.z, acc.z);
                acc.w = fmaf(c * xv.w, yv.w, acc.w);
            }
            o4[s3 * (E_DIM / 4) + lane] = acc;      // STG.128, coalesced
        }

        __syncthreads();    // all warps done with stage st before reuse
    }
}

// ---------------------------------------------------------------------------
// Launch wrapper. Inputs (metadata order):
//   0: x_table f32 [N,S*E]  1: y f32 [B,S*E]  2: path_coeff f32 [P]
//   3: x_idx i32 [B]        4: path_idx i32 [P,3]      out: f32 [B,S*E]
// ---------------------------------------------------------------------------
extern "C" void kernel_launch(void* const* d_in, const int* in_sizes, int n_in,
                              void* d_out, int out_size)
{
    const float* x_table    = (const float*)d_in[0];
    const float* y          = (const float*)d_in[1];
    const float* path_coeff = (const float*)d_in[2];
    const int*   x_idx      = (const int*)  d_in[3];
    const int*   path_idx   = (const int*)  d_in[4];
    float*       out        = (float*)d_out;

    (void)in_sizes; (void)n_in; (void)out_size;

    static int sm_count = 0;
    if (sm_count == 0) {
        cudaDeviceGetAttribute(&sm_count, cudaDevAttrMultiProcessorCount, 0);
        if (sm_count <= 0) sm_count = 148;
        cudaFuncSetAttribute(seg_poly_main,
                             cudaFuncAttributeMaxDynamicSharedMemorySize,
                             SMEM_BYTES);
    }

    seg_poly_main<<<sm_count, 32 * N_WARPS, SMEM_BYTES>>>(
        x_table, y, x_idx, path_coeff, path_idx, out);
}

// round 10
// speedup vs baseline: 1.3207x; 1.3207x over previous
#include <cuda_runtime.h>
#include <cstdint>
#include <cstddef>

// Problem constants (fixed by the dataset)
#define E_DIM 128
#define S_DIM 64
#define P_DIM 256
#define B_DIM 4096
#define ROW_FLOATS (S_DIM * E_DIM)          // 8192 floats = 32 KB
#define ROW_BYTES  (ROW_FLOATS * 4)
#define N_STAGES   3
#define N_CWARPS   8                         // compute warps
#define N_THREADS  (32 * (N_CWARPS + 1))     // +1 producer warp = 288

// ---------------------------------------------------------------------------
// Shared-memory layout (dynamic):
//   [0,24)       full mbarrier[3]   (tx-based, producer -> consumers)
//   [24,48)      empty mbarrier[3]  (8 arrivals, consumers -> producer)
//   [64,324)     seg_start[65]
//   [328,2376)   meta int2[256]     (sorted by i3)
//   [2376,3400)  prep scratch s_i3[256]
//   [3400,3660)  prep scratch s_cnt[65]
//   [4096 + st*65536) : stage st = [sx 32KB][sy 32KB]
// ---------------------------------------------------------------------------
#define OFF_FULL   0
#define OFF_EMPTY  24
#define OFF_SEG    64
#define OFF_META   328
#define OFF_I3     2376
#define OFF_CNT    3400
#define OFF_STAGE  4096
#define STAGE_BYTES (2 * ROW_BYTES)
#define SMEM_BYTES (OFF_STAGE + N_STAGES * STAGE_BYTES)   // 200704

__device__ __forceinline__ uint32_t smem_u32(const void* p) {
    uint32_t a;
    asm("{ .reg .u64 t; cvta.to.shared.u64 t, %1; cvt.u32.u64 %0, t; }"
        : "=r"(a) : "l"(p));
    return a;
}

__device__ __forceinline__ void mbar_wait(uint32_t mbar, uint32_t parity) {
    uint32_t done;
    asm volatile(
        "{\n\t"
        ".reg .pred p;\n\t"
        "mbarrier.try_wait.parity.acquire.cta.shared::cta.b64 p, [%1], %2;\n\t"
        "selp.b32 %0, 1, 0, p;\n\t"
        "}" : "=r"(done) : "r"(mbar), "r"(parity) : "memory");
    if (!done) {
        asm volatile(
            "{\n\t"
            ".reg .pred P1;\n\t"
            "W_%=:\n\t"
            "mbarrier.try_wait.parity.acquire.cta.shared::cta.b64 P1, [%0], %1, 0x989680;\n\t"
            "@P1 bra.uni D_%=;\n\t"
            "bra.uni W_%=;\n\t"
            "D_%=:\n\t"
            "}" :: "r"(mbar), "r"(parity) : "memory");
    }
}

__global__ __launch_bounds__(N_THREADS, 1)
void seg_poly_main(const float* __restrict__ x_table,
                   const float* __restrict__ y,
                   const int*   __restrict__ x_idx,
                   const float* __restrict__ path_coeff,
                   const int*   __restrict__ path_idx,
                   float*       __restrict__ out)
{
    extern __shared__ char smem[];
    int*  sseg  = (int*) (smem + OFF_SEG);
    int2* smeta = (int2*)(smem + OFF_META);
    int*  s_i3  = (int*) (smem + OFF_I3);
    int*  s_cnt = (int*) (smem + OFF_CNT);

    const int t    = threadIdx.x;            // 0..287
    const int warp = t >> 5;                 // 0..8 (8 = producer)
    const int lane = t & 31;
    const int G    = gridDim.x;
    const int r0   = blockIdx.x;

    const uint32_t full0  = smem_u32(smem + OFF_FULL);
    const uint32_t empty0 = smem_u32(smem + OFF_EMPTY);

    // --- init mbarriers ----------------------------------------------------
    if (t < N_STAGES) {
        asm volatile("mbarrier.init.shared.b64 [%0], 1;"
                     :: "r"(full0 + 8u * t) : "memory");
        asm volatile("mbarrier.init.shared.b64 [%0], %1;"
                     :: "r"(empty0 + 8u * t), "r"(N_CWARPS) : "memory");
    }
    if (t <= S_DIM) s_cnt[t] = 0;
    __syncthreads();

    // --- prep: stable counting-sort of 256 paths by i3 (non-divergent syncs)
    int i1 = 0, i2 = 0, i3 = 0;
    if (t < P_DIM) {
        i1 = path_idx[t * 3 + 0];
        i2 = path_idx[t * 3 + 1];
        i3 = path_idx[t * 3 + 2];
        s_i3[t] = i3;
    }
    __syncthreads();
    if (t < P_DIM) atomicAdd(&s_cnt[i3 + 1], 1);
    __syncthreads();
    if (t == 0) {
        int acc = 0;
        #pragma unroll
        for (int i = 0; i <= S_DIM; i++) { acc += s_cnt[i]; s_cnt[i] = acc; }
    }
    __syncthreads();
    if (t <= S_DIM) sseg[t] = s_cnt[t];
    if (t < P_DIM) {
        int rank = 0;                        // stable rank within segment
        for (int j = 0; j < t; j++) rank += (s_i3[j] == i3) ? 1 : 0;
        smeta[s_cnt[i3] + rank] =
            make_int2(((i1 * (E_DIM / 4)) << 16) | (i2 * (E_DIM / 4)),
                      __float_as_int(path_coeff[t]));
    }
    __syncthreads();                         // last CTA-wide barrier

    if (warp == N_CWARPS) {
        // ================== PRODUCER warp (lane 0 only) ====================
        if (lane == 0) {
            int k = 0;
            for (int r = r0; r < B_DIM; r += G, k++) {
                const int st = k % N_STAGES;
                const int u  = k / N_STAGES;
                if (u > 0)                       // stage reusable?
                    mbar_wait(empty0 + 8u * st, (u - 1) & 1);

                const uint32_t fb = full0 + 8u * st;
                asm volatile("mbarrier.arrive.expect_tx.shared.b64 _, [%0], %1;"
                             :: "r"(fb), "r"(STAGE_BYTES) : "memory");
                const uint32_t dst = smem_u32(smem + OFF_STAGE) + st * STAGE_BYTES;
                const char* xsrc = (const char*)(x_table + (size_t)x_idx[r] * ROW_FLOATS);
                const char* ysrc = (const char*)(y + (size_t)r * ROW_FLOATS);
                asm volatile(
                    "cp.async.bulk.shared::cta.global.mbarrier::complete_tx::bytes "
                    "[%0], [%1], %2, [%3];"
                    :: "r"(dst), "l"(xsrc), "r"(ROW_BYTES), "r"(fb) : "memory");
                asm volatile(
                    "cp.async.bulk.shared::cta.global.mbarrier::complete_tx::bytes "
                    "[%0], [%1], %2, [%3];"
                    :: "r"(dst + ROW_BYTES), "l"(ysrc), "r"(ROW_BYTES), "r"(fb) : "memory");
            }
        }
    } else {
        // ================== CONSUMER warps (0..7) ==========================
        int k = 0;
        for (int r = r0; r < B_DIM; r += G, k++) {
            const int st = k % N_STAGES;
            const int u  = k / N_STAGES;

            mbar_wait(full0 + 8u * st, u & 1);   // row data ready

            const float4* sx4 = (const float4*)(smem + OFF_STAGE + st * STAGE_BYTES);
            const float4* sy4 = sx4 + (ROW_FLOATS / 4);
            float4* o4 = (float4*)(out + (size_t)r * ROW_FLOATS);

            // warp w owns segments w, w+8, ... ; thread owns one float4 of E
            for (int s3 = warp; s3 < S_DIM; s3 += N_CWARPS) {
                const int beg = sseg[s3];
                const int end = sseg[s3 + 1];
                float4 acc = make_float4(0.f, 0.f, 0.f, 0.f);
                #pragma unroll 2
                for (int j = beg; j < end; j++) {
                    const int2  m  = smeta[j];          // LDS.64 broadcast
                    const float c  = __int_as_float(m.y);
                    const int   a1 = m.x >> 16;         // float4-unit offsets
                    const int   a2 = m.x & 0xFFFF;
                    const float4 xv = sx4[a1 + lane];   // LDS.128, conflict-free
                    const float4 yv = sy4[a2 + lane];
                    acc.x = fmaf(c * xv.x, yv.x, acc.x);
                    acc.y = fmaf(c * xv.y, yv.y, acc.y);
                    acc.z = fmaf(c * xv.z, yv.z, acc.z);
                    acc.w = fmaf(c * xv.w, yv.w, acc.w);
                }
                o4[s3 * (E_DIM / 4) + lane] = acc;      // STG.128, coalesced
            }

            // this warp is done reading stage st
            if (lane == 0) {
                asm volatile("mbarrier.arrive.shared.b64 _, [%0];"
                             :: "r"(empty0 + 8u * st) : "memory");
            }
        }
    }
}

// ---------------------------------------------------------------------------
// Launch wrapper. Inputs (metadata order):
//   0: x_table f32 [N,S*E]  1: y f32 [B,S*E]  2: path_coeff f32 [P]
//   3: x_idx i32 [B]        4: path_idx i32 [P,3]      out: f32 [B,S*E]
// ---------------------------------------------------------------------------
extern "C" void kernel_launch(void* const* d_in, const int* in_sizes, int n_in,
                              void* d_out, int out_size)
{
    const float* x_table    = (const float*)d_in[0];
    const float* y          = (const float*)d_in[1];
    const float* path_coeff = (const float*)d_in[2];
    const int*   x_idx      = (const int*)  d_in[3];
    const int*   path_idx   = (const int*)  d_in[4];
    float*       out        = (float*)d_out;

    (void)in_sizes; (void)n_in; (void)out_size;

    static int sm_count = 0;
    if (sm_count == 0) {
        cudaDeviceGetAttribute(&sm_count, cudaDevAttrMultiProcessorCount, 0);
        if (sm_count <= 0) sm_count = 148;
        cudaFuncSetAttribute(seg_poly_main,
                             cudaFuncAttributeMaxDynamicSharedMemorySize,
                             SMEM_BYTES);
    }

    seg_poly_main<<<sm_count, N_THREADS, SMEM_BYTES>>>(
        x_table, y, x_idx, path_coeff, path_idx, out);
}